// round 1
// baseline (speedup 1.0000x reference)
#include <cuda_runtime.h>
#include <math.h>

#define BQ  8
#define TT  2048
#define CC  1024
#define HH  16
#define NN  64
#define FFND 3584
#define BT  (BQ*TT)
#define EPSV 1e-5f

// ------------------------------------------------------------------
// Scratch (device globals; no dynamic allocation allowed)
// ------------------------------------------------------------------
__device__ float g_bufs[8][(size_t)BT * CC];      // 8 x 64 MB
__device__ float g_ffnb[(size_t)BT * FFND];       // 224 MB

// ------------------------------------------------------------------
// Block-wide reduction of (sum, sumsq) across 256 threads
// ------------------------------------------------------------------
__device__ __forceinline__ void block_reduce_2(float& s, float& s2) {
    __shared__ float sh[16];
    #pragma unroll
    for (int o = 16; o > 0; o >>= 1) {
        s  += __shfl_xor_sync(0xffffffffu, s,  o);
        s2 += __shfl_xor_sync(0xffffffffu, s2, o);
    }
    int wid = threadIdx.x >> 5;
    if ((threadIdx.x & 31) == 0) { sh[wid] = s; sh[8 + wid] = s2; }
    __syncthreads();
    float a = 0.f, b = 0.f;
    #pragma unroll
    for (int i = 0; i < 8; i++) { a += sh[i]; b += sh[8 + i]; }
    s = a; s2 = b;
    __syncthreads();   // make sh reusable by a second call
}

// ------------------------------------------------------------------
// Fused ln0 + ln1  (one block per row of 1024)
// ------------------------------------------------------------------
__global__ void __launch_bounds__(256) ln0ln1_kernel(
    const float* __restrict__ x,
    const float* __restrict__ w0, const float* __restrict__ b0,
    const float* __restrict__ w1, const float* __restrict__ b1,
    float* __restrict__ x0, float* __restrict__ xn)
{
    int row = blockIdx.x;
    size_t base = (size_t)row * CC;
    float v[4];
    float s = 0.f, s2 = 0.f;
    #pragma unroll
    for (int l = 0; l < 4; l++) {
        int c = l * 256 + threadIdx.x;
        v[l] = x[base + c];
        s += v[l]; s2 += v[l] * v[l];
    }
    block_reduce_2(s, s2);
    float mu = s * (1.f / CC);
    float rstd = rsqrtf(s2 * (1.f / CC) - mu * mu + EPSV);
    s = 0.f; s2 = 0.f;
    #pragma unroll
    for (int l = 0; l < 4; l++) {
        int c = l * 256 + threadIdx.x;
        float t = (v[l] - mu) * rstd * w0[c] + b0[c];
        v[l] = t;
        x0[base + c] = t;
        s += t; s2 += t * t;
    }
    block_reduce_2(s, s2);
    mu = s * (1.f / CC);
    rstd = rsqrtf(s2 * (1.f / CC) - mu * mu + EPSV);
    #pragma unroll
    for (int l = 0; l < 4; l++) {
        int c = l * 256 + threadIdx.x;
        xn[base + c] = (v[l] - mu) * rstd * w1[c] + b1[c];
    }
}

// ------------------------------------------------------------------
// Plain layernorm (one block per row)
// ------------------------------------------------------------------
__global__ void __launch_bounds__(256) ln_kernel(
    const float* __restrict__ in,
    const float* __restrict__ w, const float* __restrict__ b,
    float* __restrict__ out)
{
    int row = blockIdx.x;
    size_t base = (size_t)row * CC;
    float v[4];
    float s = 0.f, s2 = 0.f;
    #pragma unroll
    for (int l = 0; l < 4; l++) {
        int c = l * 256 + threadIdx.x;
        v[l] = in[base + c];
        s += v[l]; s2 += v[l] * v[l];
    }
    block_reduce_2(s, s2);
    float mu = s * (1.f / CC);
    float rstd = rsqrtf(s2 * (1.f / CC) - mu * mu + EPSV);
    #pragma unroll
    for (int l = 0; l < 4; l++) {
        int c = l * 256 + threadIdx.x;
        out[base + c] = (v[l] - mu) * rstd * w[c] + b[c];
    }
}

// ------------------------------------------------------------------
// Token-shift mixes
// ------------------------------------------------------------------
__global__ void __launch_bounds__(256) mix4_kernel(
    const float* __restrict__ xn,
    const float* __restrict__ tmk, const float* __restrict__ tmv,
    const float* __restrict__ tmr, const float* __restrict__ tmg,
    float* __restrict__ xk, float* __restrict__ xv,
    float* __restrict__ xr, float* __restrict__ xg)
{
    int idx = blockIdx.x * 256 + threadIdx.x;
    int c = idx & (CC - 1);
    int t = (idx >> 10) & (TT - 1);
    float a = xn[idx];
    float p = (t == 0) ? 0.f : xn[idx - CC];
    float d = a - p;
    xk[idx] = fmaf(d, tmk[c], p);
    xv[idx] = fmaf(d, tmv[c], p);
    xr[idx] = fmaf(d, tmr[c], p);
    xg[idx] = fmaf(d, tmg[c], p);
}

__global__ void __launch_bounds__(256) mix2_kernel(
    const float* __restrict__ xn,
    const float* __restrict__ tmk, const float* __restrict__ tmr,
    float* __restrict__ xk, float* __restrict__ xr)
{
    int idx = blockIdx.x * 256 + threadIdx.x;
    int c = idx & (CC - 1);
    int t = (idx >> 10) & (TT - 1);
    float a = xn[idx];
    float p = (t == 0) ? 0.f : xn[idx - CC];
    float d = a - p;
    xk[idx] = fmaf(d, tmk[c], p);
    xr[idx] = fmaf(d, tmr[c], p);
}

// ------------------------------------------------------------------
// SGEMM:  C[m,n] = sum_k A[m,k] * B[n,k]   (+ optional residual, epilogue)
// A: [M,K] row-major, B: [N,K] row-major.  M%128==0, N%128==0, K%16==0.
// EPI: 0=none  1=silu  2=relu^2  3=sigmoid
// ------------------------------------------------------------------
template<int EPI>
__global__ void __launch_bounds__(256) gemm_nt(
    const float* __restrict__ A, const float* __restrict__ B,
    const float* __restrict__ res, float* __restrict__ C,
    int M, int N, int K)
{
    __shared__ float sA[16][132];
    __shared__ float sB[16][132];
    int tid = threadIdx.x;
    int bm = blockIdx.y * 128;
    int bn = blockIdx.x * 128;
    int tx = tid & 15, ty = tid >> 4;

    const float* Ab = A + (size_t)bm * K;
    const float* Bb = B + (size_t)bn * K;

    float acc[8][8];
    #pragma unroll
    for (int i = 0; i < 8; i++)
        #pragma unroll
        for (int j = 0; j < 8; j++) acc[i][j] = 0.f;

    for (int kt = 0; kt < K; kt += 16) {
        #pragma unroll
        for (int l = 0; l < 2; l++) {
            int idx = tid + l * 256;
            int row = idx >> 2;
            int kq = (idx & 3) * 4;
            float4 va = *(const float4*)(Ab + (size_t)row * K + kt + kq);
            sA[kq + 0][row] = va.x; sA[kq + 1][row] = va.y;
            sA[kq + 2][row] = va.z; sA[kq + 3][row] = va.w;
            float4 vb = *(const float4*)(Bb + (size_t)row * K + kt + kq);
            sB[kq + 0][row] = vb.x; sB[kq + 1][row] = vb.y;
            sB[kq + 2][row] = vb.z; sB[kq + 3][row] = vb.w;
        }
        __syncthreads();
        #pragma unroll
        for (int kk = 0; kk < 16; kk++) {
            float a[8], b[8];
            *(float4*)(a + 0) = *(const float4*)&sA[kk][ty * 8 + 0];
            *(float4*)(a + 4) = *(const float4*)&sA[kk][ty * 8 + 4];
            *(float4*)(b + 0) = *(const float4*)&sB[kk][tx * 8 + 0];
            *(float4*)(b + 4) = *(const float4*)&sB[kk][tx * 8 + 4];
            #pragma unroll
            for (int i = 0; i < 8; i++)
                #pragma unroll
                for (int j = 0; j < 8; j++)
                    acc[i][j] = fmaf(a[i], b[j], acc[i][j]);
        }
        __syncthreads();
    }

    #pragma unroll
    for (int i = 0; i < 8; i++) {
        int m = bm + ty * 8 + i;
        size_t rowoff = (size_t)m * N + bn + tx * 8;
        #pragma unroll
        for (int j = 0; j < 8; j++) {
            float v = acc[i][j];
            if (res) v += res[rowoff + j];
            if (EPI == 1) v = v / (1.f + expf(-v));                 // silu
            else if (EPI == 2) { v = fmaxf(v, 0.f); v = v * v; }    // relu^2
            else if (EPI == 3) v = 1.f / (1.f + expf(-v));          // sigmoid
            C[rowoff + j] = v;
        }
    }
}

// ------------------------------------------------------------------
// wkv5 recurrence: one block per (b,h); 256 threads:
// thread = j*4 + ig, ig owns i in [ig*16, ig*16+16); S in registers.
// ------------------------------------------------------------------
__global__ void __launch_bounds__(256) wkv5_kernel(
    const float* __restrict__ r, const float* __restrict__ k,
    const float* __restrict__ v,
    const float* __restrict__ decay, const float* __restrict__ faaaa,
    float* __restrict__ out)
{
    int bh = blockIdx.x;
    int b = bh / HH, h = bh % HH;
    int tid = threadIdx.x;
    int j = tid >> 2, ig = tid & 3;

    float S[16], uu[16], ww[16];
    #pragma unroll
    for (int m = 0; m < 16; m++) {
        int i = ig * 16 + m;
        S[m] = 0.f;
        uu[m] = faaaa[h * NN + i];
        ww[m] = expf(-expf(decay[h * NN + i]));
    }

    __shared__ float sr_[NN], sk_[NN], sv_[NN];
    size_t base = ((size_t)b * TT) * CC + h * NN;

    for (int t = 0; t < TT; t++) {
        if (tid < 64)       sr_[tid]       = r[base + tid];
        else if (tid < 128) sk_[tid - 64]  = k[base + tid - 64];
        else if (tid < 192) sv_[tid - 128] = v[base + tid - 128];
        __syncthreads();

        float vj = sv_[j];
        float y = 0.f;
        #pragma unroll
        for (int m = 0; m < 16; m++) {
            int i = ig * 16 + m;
            float a = sk_[i] * vj;
            y = fmaf(sr_[i], fmaf(uu[m], a, S[m]), y);
            S[m] = fmaf(ww[m], S[m], a);
        }
        y += __shfl_xor_sync(0xffffffffu, y, 1);
        y += __shfl_xor_sync(0xffffffffu, y, 2);
        if (ig == 0) out[base + j] = y;
        __syncthreads();
        base += CC;
    }
}

// ------------------------------------------------------------------
// GroupNorm(y/8) * g  (one block per row; 16 groups of 64)
// ------------------------------------------------------------------
__global__ void __launch_bounds__(256) gn_gate_kernel(
    const float* __restrict__ y, const float* __restrict__ g,
    const float* __restrict__ w, const float* __restrict__ b,
    float* __restrict__ out)
{
    int row = blockIdx.x;
    size_t base = (size_t)row * CC;
    int gi = threadIdx.x >> 4;
    int sub = threadIdx.x & 15;
    float v[4];
    float s = 0.f, s2 = 0.f;
    #pragma unroll
    for (int l = 0; l < 4; l++) {
        int c = gi * 64 + l * 16 + sub;
        v[l] = y[base + c] * 0.125f;
        s += v[l]; s2 += v[l] * v[l];
    }
    #pragma unroll
    for (int o = 8; o > 0; o >>= 1) {
        s  += __shfl_xor_sync(0xffffffffu, s,  o);
        s2 += __shfl_xor_sync(0xffffffffu, s2, o);
    }
    float mu = s * (1.f / 64);
    float rstd = rsqrtf(s2 * (1.f / 64) - mu * mu + EPSV);
    #pragma unroll
    for (int l = 0; l < 4; l++) {
        int c = gi * 64 + l * 16 + sub;
        out[base + c] = ((v[l] - mu) * rstd * w[c] + b[c]) * g[base + c];
    }
}

// ------------------------------------------------------------------
// out = xatt + sigmoid_r * kv
// ------------------------------------------------------------------
__global__ void __launch_bounds__(256) final_kernel(
    const float* __restrict__ xatt, const float* __restrict__ sr,
    const float* __restrict__ kv, float* __restrict__ out)
{
    int idx = blockIdx.x * 256 + threadIdx.x;
    out[idx] = fmaf(sr[idx], kv[idx], xatt[idx]);
}

// ------------------------------------------------------------------
// Launch
// ------------------------------------------------------------------
extern "C" void kernel_launch(void* const* d_in, const int* in_sizes, int n_in,
                              void* d_out, int out_size)
{
    const float* x        = (const float*)d_in[0];
    const float* ln0_w    = (const float*)d_in[1];
    const float* ln0_b    = (const float*)d_in[2];
    const float* ln1_w    = (const float*)d_in[3];
    const float* ln1_b    = (const float*)d_in[4];
    const float* ln2_w    = (const float*)d_in[5];
    const float* ln2_b    = (const float*)d_in[6];
    const float* att_tmk  = (const float*)d_in[7];
    const float* att_tmv  = (const float*)d_in[8];
    const float* att_tmr  = (const float*)d_in[9];
    const float* att_tmg  = (const float*)d_in[10];
    const float* att_decay= (const float*)d_in[11];
    const float* att_faaaa= (const float*)d_in[12];
    const float* att_Wr   = (const float*)d_in[13];
    const float* att_Wk   = (const float*)d_in[14];
    const float* att_Wv   = (const float*)d_in[15];
    const float* att_Wg   = (const float*)d_in[16];
    const float* att_Wo   = (const float*)d_in[17];
    const float* lnx_w    = (const float*)d_in[18];
    const float* lnx_b    = (const float*)d_in[19];
    const float* ffn_tmk  = (const float*)d_in[20];
    const float* ffn_tmr  = (const float*)d_in[21];
    const float* ffn_Wk   = (const float*)d_in[22];
    const float* ffn_Wr   = (const float*)d_in[23];
    const float* ffn_Wv   = (const float*)d_in[24];

    float* base = nullptr;
    cudaGetSymbolAddress((void**)&base, g_bufs);
    float* FB = nullptr;
    cudaGetSymbolAddress((void**)&FB, g_ffnb);
    float* B0 = base + 0 * (size_t)BT * CC;
    float* B1 = base + 1 * (size_t)BT * CC;
    float* B2 = base + 2 * (size_t)BT * CC;
    float* B3 = base + 3 * (size_t)BT * CC;
    float* B4 = base + 4 * (size_t)BT * CC;
    float* B5 = base + 5 * (size_t)BT * CC;
    float* B6 = base + 6 * (size_t)BT * CC;
    float* B7 = base + 7 * (size_t)BT * CC;
    float* out = (float*)d_out;

    int eg = (BT * CC) / 256;                 // elementwise grid
    dim3 gC(CC / 128, BT / 128);              // N=1024 GEMMs
    dim3 gF(FFND / 128, BT / 128);            // N=3584 GEMM

    // ln0 -> B0 (residual), ln1 -> B1
    ln0ln1_kernel<<<BT, 256>>>(x, ln0_w, ln0_b, ln1_w, ln1_b, B0, B1);
    // token-shift mixes: xk=B2, xv=B3, xr=B4, xg=B5
    mix4_kernel<<<eg, 256>>>(B1, att_tmk, att_tmv, att_tmr, att_tmg, B2, B3, B4, B5);
    // projections
    gemm_nt<0><<<gC, 256>>>(B4, att_Wr, nullptr, B6, BT, CC, CC);   // r
    gemm_nt<0><<<gC, 256>>>(B2, att_Wk, nullptr, B7, BT, CC, CC);   // k
    gemm_nt<0><<<gC, 256>>>(B3, att_Wv, nullptr, B1, BT, CC, CC);   // v
    gemm_nt<1><<<gC, 256>>>(B5, att_Wg, nullptr, B2, BT, CC, CC);   // g = silu(.)
    // wkv recurrence -> B3
    wkv5_kernel<<<BQ * HH, 256>>>(B6, B7, B1, att_decay, att_faaaa, B3);
    // groupnorm(y/8) * g -> B4
    gn_gate_kernel<<<BT, 256>>>(B3, B2, lnx_w, lnx_b, B4);
    // x_att = x0 + (gy) @ Wo^T -> B5
    gemm_nt<0><<<gC, 256>>>(B4, att_Wo, B0, B5, BT, CC, CC);
    // channel mix
    ln_kernel<<<BT, 256>>>(B5, ln2_w, ln2_b, B1);
    mix2_kernel<<<eg, 256>>>(B1, ffn_tmk, ffn_tmr, B2, B3);         // xk=B2, xr=B3
    gemm_nt<2><<<gF, 256>>>(B2, ffn_Wk, nullptr, FB, BT, FFND, CC); // relu^2
    gemm_nt<0><<<gC, 256>>>(FB, ffn_Wv, nullptr, B6, BT, CC, FFND); // kv
    gemm_nt<3><<<gC, 256>>>(B3, ffn_Wr, nullptr, B7, BT, CC, CC);   // sigmoid(r)
    final_kernel<<<eg, 256>>>(B5, B7, B6, out);
}

// round 3
// speedup vs baseline: 2.4904x; 2.4904x over previous
#include <cuda_runtime.h>
#include <math.h>
#include <stdint.h>

#define BQ  8
#define TT  2048
#define CC  1024
#define HH  16
#define NN  64
#define FFND 3584
#define BT  (BQ*TT)
#define EPSV 1e-5f

// ------------------------------------------------------------------
// Scratch (device globals; no dynamic allocation allowed)
// ------------------------------------------------------------------
__device__ __align__(256) float g_bufs[8][(size_t)BT * CC];      // 8 x 64 MB
__device__ __align__(256) float g_ffnb[(size_t)BT * FFND];       // 224 MB

// ==================================================================
// PTX helpers (arch-agnostic: cp.async + ldmatrix + mma.sync only)
// ==================================================================
__device__ __forceinline__ uint32_t smem_u32(const void* p) {
    uint32_t a;
    asm("{ .reg .u64 t; cvta.to.shared.u64 t, %1; cvt.u32.u64 %0, t; }" : "=r"(a) : "l"(p));
    return a;
}
__device__ __forceinline__ void cp16(uint32_t dst, const void* src) {
    asm volatile("cp.async.cg.shared.global [%0], [%1], 16;" :: "r"(dst), "l"(src));
}
#define CP_COMMIT() asm volatile("cp.async.commit_group;" ::: "memory")
#define CP_WAIT(n)  asm volatile("cp.async.wait_group %0;" :: "n"(n) : "memory")

__device__ __forceinline__ void ldsm4(uint32_t& r0, uint32_t& r1, uint32_t& r2,
                                      uint32_t& r3, uint32_t addr) {
    asm volatile("ldmatrix.sync.aligned.m8n8.x4.shared.b16 {%0,%1,%2,%3}, [%4];"
                 : "=r"(r0), "=r"(r1), "=r"(r2), "=r"(r3) : "r"(addr));
}
__device__ __forceinline__ void mma_tf32(float* c, const uint32_t* a, const uint32_t* b) {
    asm volatile("mma.sync.aligned.m16n8k8.row.col.f32.tf32.tf32.f32 "
                 "{%0,%1,%2,%3}, {%4,%5,%6,%7}, {%8,%9}, {%0,%1,%2,%3};"
                 : "+f"(c[0]), "+f"(c[1]), "+f"(c[2]), "+f"(c[3])
                 : "r"(a[0]), "r"(a[1]), "r"(a[2]), "r"(a[3]), "r"(b[0]), "r"(b[1]));
}
__device__ __forceinline__ uint32_t swz(uint32_t off) {
    return off ^ ((off >> 3) & 0x70);   // SW128 swizzle on byte offsets
}

// ==================================================================
// tf32 mma.sync GEMM:  C[m,n] = sum_k A[m,k]*B[n,k]  (+res, epilogue)
// 128x128 CTA tile; 8 warps = 4(m) x 2(n); warp tile 32x64.
// K staged 32 floats (128B/row), SW128 swizzle, 3-stage cp.async ring.
// EPI: 0=none 1=silu 2=relu^2 3=sigmoid
// ==================================================================
#define GM_SLOTSZ 32768                 // A 16KB + B 16KB per stage
#define GM_SMEM   (3 * GM_SLOTSZ)       // 98304 bytes

__device__ __forceinline__ void load_stage(uint32_t sa, const float* Ab, const float* Bb,
                                           int K, int kt, int tid) {
    #pragma unroll
    for (int i = 0; i < 4; i++) {
        int c = tid + i * 256;
        int row = c >> 3, seg = c & 7;
        uint32_t sw = swz((uint32_t)(row * 128 + seg * 16));
        cp16(sa + sw, Ab + (size_t)row * K + kt + seg * 4);
        cp16(sa + 16384 + sw, Bb + (size_t)row * K + kt + seg * 4);
    }
}

template<int EPI>
__global__ void __launch_bounds__(256, 1) gemm_mma(
    const float* __restrict__ A, const float* __restrict__ B,
    const float* __restrict__ res, float* __restrict__ C,
    int M, int N, int K)
{
    extern __shared__ char smem[];
    uint32_t sb = smem_u32(smem);
    int tid = threadIdx.x;
    int lane = tid & 31, warp = tid >> 5;
    int wm = warp >> 1, wn = warp & 1;      // 4 x 2 warp grid
    int bm = blockIdx.y * 128;
    int bn = blockIdx.x * 128;

    const float* Ab = A + (size_t)bm * K;
    const float* Bb = B + (size_t)bn * K;
    int S = K / 32;

    // ldmatrix per-thread source row/col selectors
    int q = lane & 7, g = lane >> 3;
    int arow = wm * 32 + q + ((g & 1) << 3);          // + mf*16
    int acol4 = (g & 2) << 1;                         // 0 or 4 (+ ks*8)
    int brow = wn * 64 + q + ((g & 2) << 2);          // + p*16
    int bcol4 = (g & 1) << 2;                         // 0 or 4 (+ ks*8)

    float acc[2][8][4];
    #pragma unroll
    for (int i = 0; i < 2; i++)
        #pragma unroll
        for (int j = 0; j < 8; j++)
            #pragma unroll
            for (int l = 0; l < 4; l++) acc[i][j][l] = 0.f;

    load_stage(sb + 0 * GM_SLOTSZ, Ab, Bb, K, 0, tid);
    CP_COMMIT();
    load_stage(sb + 1 * GM_SLOTSZ, Ab, Bb, K, 32, tid);
    CP_COMMIT();

    for (int s = 0; s < S; s++) {
        CP_WAIT(1);
        __syncthreads();
        if (s + 2 < S)
            load_stage(sb + (uint32_t)((s + 2) % 3) * GM_SLOTSZ, Ab, Bb, K, (s + 2) * 32, tid);
        CP_COMMIT();

        uint32_t saA = sb + (uint32_t)(s % 3) * GM_SLOTSZ;
        uint32_t saB = saA + 16384;

        #pragma unroll
        for (int ks = 0; ks < 4; ks++) {
            uint32_t a[2][4], b[8][2];
            #pragma unroll
            for (int mf = 0; mf < 2; mf++) {
                uint32_t off = (uint32_t)((arow + mf * 16) * 128 + (ks * 8 + acol4) * 4);
                ldsm4(a[mf][0], a[mf][1], a[mf][2], a[mf][3], saA + swz(off));
            }
            #pragma unroll
            for (int p = 0; p < 4; p++) {
                uint32_t off = (uint32_t)((brow + p * 16) * 128 + (ks * 8 + bcol4) * 4);
                ldsm4(b[2 * p][0], b[2 * p][1], b[2 * p + 1][0], b[2 * p + 1][1],
                      saB + swz(off));
            }
            #pragma unroll
            for (int mf = 0; mf < 2; mf++)
                #pragma unroll
                for (int nf = 0; nf < 8; nf++)
                    mma_tf32(acc[mf][nf], a[mf], b[nf]);
        }
        __syncthreads();
    }

    // epilogue: c0,c1 -> (row, 2c,2c+1); c2,c3 -> (row+8, same cols)
    int r0 = bm + wm * 32 + (lane >> 2);
    int cbase = bn + wn * 64 + (lane & 3) * 2;
    #pragma unroll
    for (int mf = 0; mf < 2; mf++) {
        #pragma unroll
        for (int half = 0; half < 2; half++) {
            int m = r0 + mf * 16 + half * 8;
            size_t rowoff = (size_t)m * N + cbase;
            #pragma unroll
            for (int nf = 0; nf < 8; nf++) {
                float2 v;
                v.x = acc[mf][nf][half * 2 + 0];
                v.y = acc[mf][nf][half * 2 + 1];
                size_t o = rowoff + nf * 8;
                if (res) {
                    float2 rv = *(const float2*)(res + o);
                    v.x += rv.x; v.y += rv.y;
                }
                if (EPI == 1) {
                    v.x = v.x / (1.f + expf(-v.x)); v.y = v.y / (1.f + expf(-v.y));
                } else if (EPI == 2) {
                    v.x = fmaxf(v.x, 0.f); v.x *= v.x;
                    v.y = fmaxf(v.y, 0.f); v.y *= v.y;
                } else if (EPI == 3) {
                    v.x = 1.f / (1.f + expf(-v.x)); v.y = 1.f / (1.f + expf(-v.y));
                }
                *(float2*)(C + o) = v;
            }
        }
    }
}

// ------------------------------------------------------------------
// Block-wide reduction of (sum, sumsq) across 256 threads
// ------------------------------------------------------------------
__device__ __forceinline__ void block_reduce_2(float& s, float& s2) {
    __shared__ float sh[16];
    #pragma unroll
    for (int o = 16; o > 0; o >>= 1) {
        s  += __shfl_xor_sync(0xffffffffu, s,  o);
        s2 += __shfl_xor_sync(0xffffffffu, s2, o);
    }
    int wid = threadIdx.x >> 5;
    if ((threadIdx.x & 31) == 0) { sh[wid] = s; sh[8 + wid] = s2; }
    __syncthreads();
    float a = 0.f, b = 0.f;
    #pragma unroll
    for (int i = 0; i < 8; i++) { a += sh[i]; b += sh[8 + i]; }
    s = a; s2 = b;
    __syncthreads();
}

// ------------------------------------------------------------------
// Fused ln0 + ln1  (one block per row of 1024)
// ------------------------------------------------------------------
__global__ void __launch_bounds__(256) ln0ln1_kernel(
    const float* __restrict__ x,
    const float* __restrict__ w0, const float* __restrict__ b0,
    const float* __restrict__ w1, const float* __restrict__ b1,
    float* __restrict__ x0, float* __restrict__ xn)
{
    int row = blockIdx.x;
    size_t base = (size_t)row * CC;
    float v[4];
    float s = 0.f, s2 = 0.f;
    #pragma unroll
    for (int l = 0; l < 4; l++) {
        int c = l * 256 + threadIdx.x;
        v[l] = x[base + c];
        s += v[l]; s2 += v[l] * v[l];
    }
    block_reduce_2(s, s2);
    float mu = s * (1.f / CC);
    float rstd = rsqrtf(s2 * (1.f / CC) - mu * mu + EPSV);
    s = 0.f; s2 = 0.f;
    #pragma unroll
    for (int l = 0; l < 4; l++) {
        int c = l * 256 + threadIdx.x;
        float t = (v[l] - mu) * rstd * w0[c] + b0[c];
        v[l] = t;
        x0[base + c] = t;
        s += t; s2 += t * t;
    }
    block_reduce_2(s, s2);
    mu = s * (1.f / CC);
    rstd = rsqrtf(s2 * (1.f / CC) - mu * mu + EPSV);
    #pragma unroll
    for (int l = 0; l < 4; l++) {
        int c = l * 256 + threadIdx.x;
        xn[base + c] = (v[l] - mu) * rstd * w1[c] + b1[c];
    }
}

// ------------------------------------------------------------------
// Plain layernorm (one block per row)
// ------------------------------------------------------------------
__global__ void __launch_bounds__(256) ln_kernel(
    const float* __restrict__ in,
    const float* __restrict__ w, const float* __restrict__ b,
    float* __restrict__ out)
{
    int row = blockIdx.x;
    size_t base = (size_t)row * CC;
    float v[4];
    float s = 0.f, s2 = 0.f;
    #pragma unroll
    for (int l = 0; l < 4; l++) {
        int c = l * 256 + threadIdx.x;
        v[l] = in[base + c];
        s += v[l]; s2 += v[l] * v[l];
    }
    block_reduce_2(s, s2);
    float mu = s * (1.f / CC);
    float rstd = rsqrtf(s2 * (1.f / CC) - mu * mu + EPSV);
    #pragma unroll
    for (int l = 0; l < 4; l++) {
        int c = l * 256 + threadIdx.x;
        out[base + c] = (v[l] - mu) * rstd * w[c] + b[c];
    }
}

// ------------------------------------------------------------------
// Token-shift mixes
// ------------------------------------------------------------------
__global__ void __launch_bounds__(256) mix4_kernel(
    const float* __restrict__ xn,
    const float* __restrict__ tmk, const float* __restrict__ tmv,
    const float* __restrict__ tmr, const float* __restrict__ tmg,
    float* __restrict__ xk, float* __restrict__ xv,
    float* __restrict__ xr, float* __restrict__ xg)
{
    int idx = blockIdx.x * 256 + threadIdx.x;
    int c = idx & (CC - 1);
    int t = (idx >> 10) & (TT - 1);
    float a = xn[idx];
    float p = (t == 0) ? 0.f : xn[idx - CC];
    float d = a - p;
    xk[idx] = fmaf(d, tmk[c], p);
    xv[idx] = fmaf(d, tmv[c], p);
    xr[idx] = fmaf(d, tmr[c], p);
    xg[idx] = fmaf(d, tmg[c], p);
}

__global__ void __launch_bounds__(256) mix2_kernel(
    const float* __restrict__ xn,
    const float* __restrict__ tmk, const float* __restrict__ tmr,
    float* __restrict__ xk, float* __restrict__ xr)
{
    int idx = blockIdx.x * 256 + threadIdx.x;
    int c = idx & (CC - 1);
    int t = (idx >> 10) & (TT - 1);
    float a = xn[idx];
    float p = (t == 0) ? 0.f : xn[idx - CC];
    float d = a - p;
    xk[idx] = fmaf(d, tmk[c], p);
    xr[idx] = fmaf(d, tmr[c], p);
}

// ------------------------------------------------------------------
// wkv5 recurrence: one block per (b,h); 256 threads.
// ------------------------------------------------------------------
__global__ void __launch_bounds__(256) wkv5_kernel(
    const float* __restrict__ r, const float* __restrict__ k,
    const float* __restrict__ v,
    const float* __restrict__ decay, const float* __restrict__ faaaa,
    float* __restrict__ out)
{
    int bh = blockIdx.x;
    int b = bh / HH, h = bh % HH;
    int tid = threadIdx.x;
    int j = tid >> 2, ig = tid & 3;

    float S[16], uu[16], ww[16];
    #pragma unroll
    for (int m = 0; m < 16; m++) {
        int i = ig * 16 + m;
        S[m] = 0.f;
        uu[m] = faaaa[h * NN + i];
        ww[m] = expf(-expf(decay[h * NN + i]));
    }

    __shared__ float sr_[NN], sk_[NN], sv_[NN];
    size_t base = ((size_t)b * TT) * CC + h * NN;

    for (int t = 0; t < TT; t++) {
        if (tid < 64)       sr_[tid]       = r[base + tid];
        else if (tid < 128) sk_[tid - 64]  = k[base + tid - 64];
        else if (tid < 192) sv_[tid - 128] = v[base + tid - 128];
        __syncthreads();

        float vj = sv_[j];
        float y = 0.f;
        #pragma unroll
        for (int m = 0; m < 16; m++) {
            int i = ig * 16 + m;
            float a = sk_[i] * vj;
            y = fmaf(sr_[i], fmaf(uu[m], a, S[m]), y);
            S[m] = fmaf(ww[m], S[m], a);
        }
        y += __shfl_xor_sync(0xffffffffu, y, 1);
        y += __shfl_xor_sync(0xffffffffu, y, 2);
        if (ig == 0) out[base + j] = y;
        __syncthreads();
        base += CC;
    }
}

// ------------------------------------------------------------------
// GroupNorm(y/8) * g  (one block per row; 16 groups of 64)
// ------------------------------------------------------------------
__global__ void __launch_bounds__(256) gn_gate_kernel(
    const float* __restrict__ y, const float* __restrict__ g,
    const float* __restrict__ w, const float* __restrict__ b,
    float* __restrict__ out)
{
    int row = blockIdx.x;
    size_t base = (size_t)row * CC;
    int gi = threadIdx.x >> 4;
    int sub = threadIdx.x & 15;
    float v[4];
    float s = 0.f, s2 = 0.f;
    #pragma unroll
    for (int l = 0; l < 4; l++) {
        int c = gi * 64 + l * 16 + sub;
        v[l] = y[base + c] * 0.125f;
        s += v[l]; s2 += v[l] * v[l];
    }
    #pragma unroll
    for (int o = 8; o > 0; o >>= 1) {
        s  += __shfl_xor_sync(0xffffffffu, s,  o);
        s2 += __shfl_xor_sync(0xffffffffu, s2, o);
    }
    float mu = s * (1.f / 64);
    float rstd = rsqrtf(s2 * (1.f / 64) - mu * mu + EPSV);
    #pragma unroll
    for (int l = 0; l < 4; l++) {
        int c = gi * 64 + l * 16 + sub;
        out[base + c] = ((v[l] - mu) * rstd * w[c] + b[c]) * g[base + c];
    }
}

// ------------------------------------------------------------------
// out = xatt + sigmoid_r * kv
// ------------------------------------------------------------------
__global__ void __launch_bounds__(256) final_kernel(
    const float* __restrict__ xatt, const float* __restrict__ sr,
    const float* __restrict__ kv, float* __restrict__ out)
{
    int idx = blockIdx.x * 256 + threadIdx.x;
    out[idx] = fmaf(sr[idx], kv[idx], xatt[idx]);
}

// ------------------------------------------------------------------
// Launch
// ------------------------------------------------------------------
extern "C" void kernel_launch(void* const* d_in, const int* in_sizes, int n_in,
                              void* d_out, int out_size)
{
    const float* x        = (const float*)d_in[0];
    const float* ln0_w    = (const float*)d_in[1];
    const float* ln0_b    = (const float*)d_in[2];
    const float* ln1_w    = (const float*)d_in[3];
    const float* ln1_b    = (const float*)d_in[4];
    const float* ln2_w    = (const float*)d_in[5];
    const float* ln2_b    = (const float*)d_in[6];
    const float* att_tmk  = (const float*)d_in[7];
    const float* att_tmv  = (const float*)d_in[8];
    const float* att_tmr  = (const float*)d_in[9];
    const float* att_tmg  = (const float*)d_in[10];
    const float* att_decay= (const float*)d_in[11];
    const float* att_faaaa= (const float*)d_in[12];
    const float* att_Wr   = (const float*)d_in[13];
    const float* att_Wk   = (const float*)d_in[14];
    const float* att_Wv   = (const float*)d_in[15];
    const float* att_Wg   = (const float*)d_in[16];
    const float* att_Wo   = (const float*)d_in[17];
    const float* lnx_w    = (const float*)d_in[18];
    const float* lnx_b    = (const float*)d_in[19];
    const float* ffn_tmk  = (const float*)d_in[20];
    const float* ffn_tmr  = (const float*)d_in[21];
    const float* ffn_Wk   = (const float*)d_in[22];
    const float* ffn_Wr   = (const float*)d_in[23];
    const float* ffn_Wv   = (const float*)d_in[24];

    float* base = nullptr;
    cudaGetSymbolAddress((void**)&base, g_bufs);
    float* FB = nullptr;
    cudaGetSymbolAddress((void**)&FB, g_ffnb);
    float* B0 = base + 0 * (size_t)BT * CC;
    float* B1 = base + 1 * (size_t)BT * CC;
    float* B2 = base + 2 * (size_t)BT * CC;
    float* B3 = base + 3 * (size_t)BT * CC;
    float* B4 = base + 4 * (size_t)BT * CC;
    float* B5 = base + 5 * (size_t)BT * CC;
    float* B6 = base + 6 * (size_t)BT * CC;
    float* B7 = base + 7 * (size_t)BT * CC;
    float* out = (float*)d_out;

    cudaFuncSetAttribute(gemm_mma<0>, cudaFuncAttributeMaxDynamicSharedMemorySize, GM_SMEM);
    cudaFuncSetAttribute(gemm_mma<1>, cudaFuncAttributeMaxDynamicSharedMemorySize, GM_SMEM);
    cudaFuncSetAttribute(gemm_mma<2>, cudaFuncAttributeMaxDynamicSharedMemorySize, GM_SMEM);
    cudaFuncSetAttribute(gemm_mma<3>, cudaFuncAttributeMaxDynamicSharedMemorySize, GM_SMEM);

    int eg = (BT * CC) / 256;                 // elementwise grid
    dim3 gC(CC / 128, BT / 128);              // N=1024 GEMMs
    dim3 gF(FFND / 128, BT / 128);            // N=3584 GEMM

    // ln0 -> B0 (residual), ln1 -> B1
    ln0ln1_kernel<<<BT, 256>>>(x, ln0_w, ln0_b, ln1_w, ln1_b, B0, B1);
    // token-shift mixes: xk=B2, xv=B3, xr=B4, xg=B5
    mix4_kernel<<<eg, 256>>>(B1, att_tmk, att_tmv, att_tmr, att_tmg, B2, B3, B4, B5);
    // projections
    gemm_mma<0><<<gC, 256, GM_SMEM>>>(B4, att_Wr, nullptr, B6, BT, CC, CC);   // r
    gemm_mma<0><<<gC, 256, GM_SMEM>>>(B2, att_Wk, nullptr, B7, BT, CC, CC);   // k
    gemm_mma<0><<<gC, 256, GM_SMEM>>>(B3, att_Wv, nullptr, B1, BT, CC, CC);   // v
    gemm_mma<1><<<gC, 256, GM_SMEM>>>(B5, att_Wg, nullptr, B2, BT, CC, CC);   // g = silu
    // wkv recurrence -> B3
    wkv5_kernel<<<BQ * HH, 256>>>(B6, B7, B1, att_decay, att_faaaa, B3);
    // groupnorm(y/8) * g -> B4
    gn_gate_kernel<<<BT, 256>>>(B3, B2, lnx_w, lnx_b, B4);
    // x_att = x0 + (gy) @ Wo^T -> B5
    gemm_mma<0><<<gC, 256, GM_SMEM>>>(B4, att_Wo, B0, B5, BT, CC, CC);
    // channel mix
    ln_kernel<<<BT, 256>>>(B5, ln2_w, ln2_b, B1);
    mix2_kernel<<<eg, 256>>>(B1, ffn_tmk, ffn_tmr, B2, B3);         // xk=B2, xr=B3
    gemm_mma<2><<<gF, 256, GM_SMEM>>>(B2, ffn_Wk, nullptr, FB, BT, FFND, CC); // relu^2
    gemm_mma<0><<<gC, 256, GM_SMEM>>>(FB, ffn_Wv, nullptr, B6, BT, CC, FFND); // kv
    gemm_mma<3><<<gC, 256, GM_SMEM>>>(B3, ffn_Wr, nullptr, B7, BT, CC, CC);   // sigmoid(r)
    final_kernel<<<eg, 256>>>(B5, B7, B6, out);
}

// round 5
// speedup vs baseline: 3.2403x; 1.3011x over previous
#include <cuda_runtime.h>
#include <math.h>
#include <stdint.h>

#define BQ  8
#define TT  2048
#define CC  1024
#define HH  16
#define NN  64
#define FFND 3584
#define BT  (BQ*TT)
#define EPSV 1e-5f

// ------------------------------------------------------------------
// Scratch (device globals; no dynamic allocation allowed)
// ------------------------------------------------------------------
__device__ __align__(256) float g_bufs[8][(size_t)BT * CC];      // 8 x 64 MB
__device__ __align__(256) float g_ffnb[(size_t)BT * FFND];       // 224 MB

// ==================================================================
// PTX helpers (arch-agnostic: cp.async + ldmatrix + mma.sync only)
// ==================================================================
__device__ __forceinline__ uint32_t smem_u32(const void* p) {
    uint32_t a;
    asm("{ .reg .u64 t; cvta.to.shared.u64 t, %1; cvt.u32.u64 %0, t; }" : "=r"(a) : "l"(p));
    return a;
}
__device__ __forceinline__ void cp16(uint32_t dst, const void* src) {
    asm volatile("cp.async.cg.shared.global [%0], [%1], 16;" :: "r"(dst), "l"(src));
}
#define CP_COMMIT() asm volatile("cp.async.commit_group;" ::: "memory")
#define CP_WAIT(n)  asm volatile("cp.async.wait_group %0;" :: "n"(n) : "memory")

__device__ __forceinline__ void ldsm4(uint32_t& r0, uint32_t& r1, uint32_t& r2,
                                      uint32_t& r3, uint32_t addr) {
    asm volatile("ldmatrix.sync.aligned.m8n8.x4.shared.b16 {%0,%1,%2,%3}, [%4];"
                 : "=r"(r0), "=r"(r1), "=r"(r2), "=r"(r3) : "r"(addr));
}
__device__ __forceinline__ void mma_tf32(float* c, const uint32_t* a, const uint32_t* b) {
    asm volatile("mma.sync.aligned.m16n8k8.row.col.f32.tf32.tf32.f32 "
                 "{%0,%1,%2,%3}, {%4,%5,%6,%7}, {%8,%9}, {%0,%1,%2,%3};"
                 : "+f"(c[0]), "+f"(c[1]), "+f"(c[2]), "+f"(c[3])
                 : "r"(a[0]), "r"(a[1]), "r"(a[2]), "r"(a[3]), "r"(b[0]), "r"(b[1]));
}
__device__ __forceinline__ uint32_t swz(uint32_t off) {
    return off ^ ((off >> 3) & 0x70);   // SW128 swizzle on byte offsets
}

// ==================================================================
// tf32 mma.sync GEMM:  C[m,n] = sum_k A[m,k]*B[n,k]  (+res, epilogue)
// 128x128 CTA tile; 8 warps = 4(m) x 2(n); warp tile 32x64.
// K staged 32 floats (128B/row), SW128 swizzle, 3-stage cp.async ring,
// ks-level fragment double-buffering, single barrier per stage.
// EPI: 0=none 1=silu 2=relu^2 3=sigmoid
// ==================================================================
#define GM_SLOTSZ 32768                 // A 16KB + B 16KB per stage
#define GM_SMEM   (3 * GM_SLOTSZ)       // 98304 bytes

__device__ __forceinline__ void load_stage(uint32_t sa, const float* Ab, const float* Bb,
                                           int K, int kt, int tid) {
    #pragma unroll
    for (int i = 0; i < 4; i++) {
        int c = tid + i * 256;
        int row = c >> 3, seg = c & 7;
        uint32_t sw = swz((uint32_t)(row * 128 + seg * 16));
        cp16(sa + sw, Ab + (size_t)row * K + kt + seg * 4);
        cp16(sa + 16384 + sw, Bb + (size_t)row * K + kt + seg * 4);
    }
}

__device__ __forceinline__ void load_frags(uint32_t saA, uint32_t saB, int ks,
                                           int arow, int acol4, int brow, int bcol4,
                                           uint32_t a[2][4], uint32_t b[8][2]) {
    #pragma unroll
    for (int mf = 0; mf < 2; mf++) {
        uint32_t off = (uint32_t)((arow + mf * 16) * 128 + (ks * 8 + acol4) * 4);
        ldsm4(a[mf][0], a[mf][1], a[mf][2], a[mf][3], saA + swz(off));
    }
    #pragma unroll
    for (int p = 0; p < 4; p++) {
        uint32_t off = (uint32_t)((brow + p * 16) * 128 + (ks * 8 + bcol4) * 4);
        ldsm4(b[2 * p][0], b[2 * p][1], b[2 * p + 1][0], b[2 * p + 1][1], saB + swz(off));
    }
}

template<int EPI>
__global__ void __launch_bounds__(256, 1) gemm_mma(
    const float* __restrict__ A, const float* __restrict__ B,
    const float* __restrict__ res, float* __restrict__ C,
    int M, int N, int K)
{
    extern __shared__ char smem[];
    uint32_t sb = smem_u32(smem);
    int tid = threadIdx.x;
    int lane = tid & 31, warp = tid >> 5;
    int wm = warp >> 1, wn = warp & 1;      // 4 x 2 warp grid
    int bm = blockIdx.y * 128;
    int bn = blockIdx.x * 128;

    const float* Ab = A + (size_t)bm * K;
    const float* Bb = B + (size_t)bn * K;
    int S = K / 32;

    // ldmatrix per-thread source row/col selectors
    int q = lane & 7, g = lane >> 3;
    int arow = wm * 32 + q + ((g & 1) << 3);          // + mf*16
    int acol4 = (g & 2) << 1;                         // 0 or 4 (+ ks*8)
    int brow = wn * 64 + q + ((g & 2) << 2);          // + p*16
    int bcol4 = (g & 1) << 2;                         // 0 or 4 (+ ks*8)

    float acc[2][8][4];
    #pragma unroll
    for (int i = 0; i < 2; i++)
        #pragma unroll
        for (int j = 0; j < 8; j++)
            #pragma unroll
            for (int l = 0; l < 4; l++) acc[i][j][l] = 0.f;

    load_stage(sb + 0 * GM_SLOTSZ, Ab, Bb, K, 0, tid);
    CP_COMMIT();
    load_stage(sb + 1 * GM_SLOTSZ, Ab, Bb, K, 32, tid);
    CP_COMMIT();

    uint32_t af[2][2][4], bf[2][8][2];

    for (int s = 0; s < S; s++) {
        CP_WAIT(1);
        __syncthreads();
        // prefetch next stage (slot consumed 2 stages ago; barrier above protects)
        if (s + 2 < S)
            load_stage(sb + (uint32_t)((s + 2) % 3) * GM_SLOTSZ, Ab, Bb, K, (s + 2) * 32, tid);
        CP_COMMIT();

        uint32_t saA = sb + (uint32_t)(s % 3) * GM_SLOTSZ;
        uint32_t saB = saA + 16384;

        load_frags(saA, saB, 0, arow, acol4, brow, bcol4, af[0], bf[0]);
        #pragma unroll
        for (int ks = 0; ks < 4; ks++) {
            if (ks < 3)
                load_frags(saA, saB, ks + 1, arow, acol4, brow, bcol4,
                           af[(ks + 1) & 1], bf[(ks + 1) & 1]);
            #pragma unroll
            for (int mf = 0; mf < 2; mf++)
                #pragma unroll
                for (int nf = 0; nf < 8; nf++)
                    mma_tf32(acc[mf][nf], af[ks & 1][mf], bf[ks & 1][nf]);
        }
        // no bottom barrier: next iteration's top barrier protects slot reuse
    }

    // epilogue: c0,c1 -> (row, 2c,2c+1); c2,c3 -> (row+8, same cols)
    int r0 = bm + wm * 32 + (lane >> 2);
    int cbase = bn + wn * 64 + (lane & 3) * 2;
    #pragma unroll
    for (int mf = 0; mf < 2; mf++) {
        #pragma unroll
        for (int half = 0; half < 2; half++) {
            int m = r0 + mf * 16 + half * 8;
            size_t rowoff = (size_t)m * N + cbase;
            #pragma unroll
            for (int nf = 0; nf < 8; nf++) {
                float2 v;
                v.x = acc[mf][nf][half * 2 + 0];
                v.y = acc[mf][nf][half * 2 + 1];
                size_t o = rowoff + nf * 8;
                if (res) {
                    float2 rv = *(const float2*)(res + o);
                    v.x += rv.x; v.y += rv.y;
                }
                if (EPI == 1) {
                    v.x = v.x / (1.f + expf(-v.x)); v.y = v.y / (1.f + expf(-v.y));
                } else if (EPI == 2) {
                    v.x = fmaxf(v.x, 0.f); v.x *= v.x;
                    v.y = fmaxf(v.y, 0.f); v.y *= v.y;
                } else if (EPI == 3) {
                    v.x = 1.f / (1.f + expf(-v.x)); v.y = 1.f / (1.f + expf(-v.y));
                }
                *(float2*)(C + o) = v;
            }
        }
    }
}

// ------------------------------------------------------------------
// Block-wide reduction of (sum, sumsq) across 256 threads
// ------------------------------------------------------------------
__device__ __forceinline__ void block_reduce_2(float& s, float& s2) {
    __shared__ float sh[16];
    #pragma unroll
    for (int o = 16; o > 0; o >>= 1) {
        s  += __shfl_xor_sync(0xffffffffu, s,  o);
        s2 += __shfl_xor_sync(0xffffffffu, s2, o);
    }
    int wid = threadIdx.x >> 5;
    if ((threadIdx.x & 31) == 0) { sh[wid] = s; sh[8 + wid] = s2; }
    __syncthreads();
    float a = 0.f, b = 0.f;
    #pragma unroll
    for (int i = 0; i < 8; i++) { a += sh[i]; b += sh[8 + i]; }
    s = a; s2 = b;
    __syncthreads();
}

// ------------------------------------------------------------------
// Fused ln0 + ln1  (one block per row of 1024)
// ------------------------------------------------------------------
__global__ void __launch_bounds__(256) ln0ln1_kernel(
    const float* __restrict__ x,
    const float* __restrict__ w0, const float* __restrict__ b0,
    const float* __restrict__ w1, const float* __restrict__ b1,
    float* __restrict__ x0, float* __restrict__ xn)
{
    int row = blockIdx.x;
    size_t base = (size_t)row * CC;
    float v[4];
    float s = 0.f, s2 = 0.f;
    #pragma unroll
    for (int l = 0; l < 4; l++) {
        int c = l * 256 + threadIdx.x;
        v[l] = x[base + c];
        s += v[l]; s2 += v[l] * v[l];
    }
    block_reduce_2(s, s2);
    float mu = s * (1.f / CC);
    float rstd = rsqrtf(s2 * (1.f / CC) - mu * mu + EPSV);
    s = 0.f; s2 = 0.f;
    #pragma unroll
    for (int l = 0; l < 4; l++) {
        int c = l * 256 + threadIdx.x;
        float t = (v[l] - mu) * rstd * w0[c] + b0[c];
        v[l] = t;
        x0[base + c] = t;
        s += t; s2 += t * t;
    }
    block_reduce_2(s, s2);
    mu = s * (1.f / CC);
    rstd = rsqrtf(s2 * (1.f / CC) - mu * mu + EPSV);
    #pragma unroll
    for (int l = 0; l < 4; l++) {
        int c = l * 256 + threadIdx.x;
        xn[base + c] = (v[l] - mu) * rstd * w1[c] + b1[c];
    }
}

// ------------------------------------------------------------------
// Plain layernorm (one block per row)
// ------------------------------------------------------------------
__global__ void __launch_bounds__(256) ln_kernel(
    const float* __restrict__ in,
    const float* __restrict__ w, const float* __restrict__ b,
    float* __restrict__ out)
{
    int row = blockIdx.x;
    size_t base = (size_t)row * CC;
    float v[4];
    float s = 0.f, s2 = 0.f;
    #pragma unroll
    for (int l = 0; l < 4; l++) {
        int c = l * 256 + threadIdx.x;
        v[l] = in[base + c];
        s += v[l]; s2 += v[l] * v[l];
    }
    block_reduce_2(s, s2);
    float mu = s * (1.f / CC);
    float rstd = rsqrtf(s2 * (1.f / CC) - mu * mu + EPSV);
    #pragma unroll
    for (int l = 0; l < 4; l++) {
        int c = l * 256 + threadIdx.x;
        out[base + c] = (v[l] - mu) * rstd * w[c] + b[c];
    }
}

// ------------------------------------------------------------------
// Token-shift mixes (float4 vectorized; 1024 floats per row)
// ------------------------------------------------------------------
__global__ void __launch_bounds__(256) mix4_kernel(
    const float4* __restrict__ xn,
    const float4* __restrict__ tmk, const float4* __restrict__ tmv,
    const float4* __restrict__ tmr, const float4* __restrict__ tmg,
    float4* __restrict__ xk, float4* __restrict__ xv,
    float4* __restrict__ xr, float4* __restrict__ xg)
{
    int idx = blockIdx.x * 256 + threadIdx.x;      // in float4 units
    int c = idx & (CC / 4 - 1);
    int t = (idx >> 8) & (TT - 1);
    float4 a = xn[idx];
    float4 p = make_float4(0.f, 0.f, 0.f, 0.f);
    if (t != 0) p = xn[idx - CC / 4];
    float4 dk = tmk[c], dv = tmv[c], dr = tmr[c], dg = tmg[c];
    float dx = a.x - p.x, dy = a.y - p.y, dz = a.z - p.z, dw = a.w - p.w;
    xk[idx] = make_float4(fmaf(dx, dk.x, p.x), fmaf(dy, dk.y, p.y),
                          fmaf(dz, dk.z, p.z), fmaf(dw, dk.w, p.w));
    xv[idx] = make_float4(fmaf(dx, dv.x, p.x), fmaf(dy, dv.y, p.y),
                          fmaf(dz, dv.z, p.z), fmaf(dw, dv.w, p.w));
    xr[idx] = make_float4(fmaf(dx, dr.x, p.x), fmaf(dy, dr.y, p.y),
                          fmaf(dz, dr.z, p.z), fmaf(dw, dr.w, p.w));
    xg[idx] = make_float4(fmaf(dx, dg.x, p.x), fmaf(dy, dg.y, p.y),
                          fmaf(dz, dg.z, p.z), fmaf(dw, dg.w, p.w));
}

__global__ void __launch_bounds__(256) mix2_kernel(
    const float4* __restrict__ xn,
    const float4* __restrict__ tmk, const float4* __restrict__ tmr,
    float4* __restrict__ xk, float4* __restrict__ xr)
{
    int idx = blockIdx.x * 256 + threadIdx.x;
    int c = idx & (CC / 4 - 1);
    int t = (idx >> 8) & (TT - 1);
    float4 a = xn[idx];
    float4 p = make_float4(0.f, 0.f, 0.f, 0.f);
    if (t != 0) p = xn[idx - CC / 4];
    float4 dk = tmk[c], dr = tmr[c];
    float dx = a.x - p.x, dy = a.y - p.y, dz = a.z - p.z, dw = a.w - p.w;
    xk[idx] = make_float4(fmaf(dx, dk.x, p.x), fmaf(dy, dk.y, p.y),
                          fmaf(dz, dk.z, p.z), fmaf(dw, dk.w, p.w));
    xr[idx] = make_float4(fmaf(dx, dr.x, p.x), fmaf(dy, dr.y, p.y),
                          fmaf(dz, dr.z, p.z), fmaf(dw, dr.w, p.w));
}

// ------------------------------------------------------------------
// wkv5 recurrence: one block per (b,h); 256 threads.
// 3-slot cp.async ring over timesteps; one barrier per step.
// ------------------------------------------------------------------
__global__ void __launch_bounds__(256) wkv5_kernel(
    const float* __restrict__ r, const float* __restrict__ k,
    const float* __restrict__ v,
    const float* __restrict__ decay, const float* __restrict__ faaaa,
    float* __restrict__ out)
{
    int bh = blockIdx.x;
    int b = bh / HH, h = bh % HH;
    int tid = threadIdx.x;
    int j = tid >> 2, ig = tid & 3;

    float S[16], uu[16], ww[16];
    #pragma unroll
    for (int m = 0; m < 16; m++) {
        int i = ig * 16 + m;
        S[m] = 0.f;
        uu[m] = faaaa[h * NN + i];
        ww[m] = expf(-expf(decay[h * NN + i]));
    }

    // slot layout: [r(64) | k(64) | v(64)] floats per slot, 3 slots
    __shared__ __align__(16) float buf[3 * 192];
    uint32_t sbuf = smem_u32(buf);

    size_t base = ((size_t)b * TT) * CC + h * NN;   // advances by CC per step

    // issue one 16B cp per thread (tid<48): tid 0-15 r, 16-31 k, 32-47 v
    const float* srcs[3] = { r, k, v };
    int part = tid >> 4;                 // 0,1,2 for tid<48
    int off4 = (tid & 15) * 4;           // float offset within 64

    // prologue: loads for t=0,1
    #pragma unroll
    for (int t = 0; t < 2; t++) {
        if (tid < 48)
            cp16(sbuf + (uint32_t)(t * 192 + part * 64 + off4) * 4,
                 srcs[part] + base + (size_t)t * CC + off4);
        CP_COMMIT();
    }

    for (int t = 0; t < TT; t++) {
        CP_WAIT(1);
        __syncthreads();                 // slot t resident & visible; all done with t-1
        if (t + 2 < TT && tid < 48)
            cp16(sbuf + (uint32_t)(((t + 2) % 3) * 192 + part * 64 + off4) * 4,
                 srcs[part] + base + (size_t)(t + 2) * CC + off4);
        CP_COMMIT();

        const float* sl = buf + (t % 3) * 192;
        float vj = sl[128 + j];
        float y = 0.f;
        #pragma unroll
        for (int m = 0; m < 16; m++) {
            int i = ig * 16 + m;
            float a = sl[64 + i] * vj;
            y = fmaf(sl[i], fmaf(uu[m], a, S[m]), y);
            S[m] = fmaf(ww[m], S[m], a);
        }
        y += __shfl_xor_sync(0xffffffffu, y, 1);
        y += __shfl_xor_sync(0xffffffffu, y, 2);
        if (ig == 0) out[base + (size_t)t * CC + j] = y;
    }
}

// ------------------------------------------------------------------
// GroupNorm(y/8) * g  (one block per row; 16 groups of 64)
// ------------------------------------------------------------------
__global__ void __launch_bounds__(256) gn_gate_kernel(
    const float* __restrict__ y, const float* __restrict__ g,
    const float* __restrict__ w, const float* __restrict__ b,
    float* __restrict__ out)
{
    int row = blockIdx.x;
    size_t base = (size_t)row * CC;
    int gi = threadIdx.x >> 4;
    int sub = threadIdx.x & 15;
    float v[4];
    float s = 0.f, s2 = 0.f;
    #pragma unroll
    for (int l = 0; l < 4; l++) {
        int c = gi * 64 + l * 16 + sub;
        v[l] = y[base + c] * 0.125f;
        s += v[l]; s2 += v[l] * v[l];
    }
    #pragma unroll
    for (int o = 8; o > 0; o >>= 1) {
        s  += __shfl_xor_sync(0xffffffffu, s,  o);
        s2 += __shfl_xor_sync(0xffffffffu, s2, o);
    }
    float mu = s * (1.f / 64);
    float rstd = rsqrtf(s2 * (1.f / 64) - mu * mu + EPSV);
    #pragma unroll
    for (int l = 0; l < 4; l++) {
        int c = gi * 64 + l * 16 + sub;
        out[base + c] = ((v[l] - mu) * rstd * w[c] + b[c]) * g[base + c];
    }
}

// ------------------------------------------------------------------
// out = xatt + sigmoid_r * kv   (float4)
// ------------------------------------------------------------------
__global__ void __launch_bounds__(256) final_kernel(
    const float4* __restrict__ xatt, const float4* __restrict__ sr,
    const float4* __restrict__ kv, float4* __restrict__ out)
{
    int idx = blockIdx.x * 256 + threadIdx.x;
    float4 a = xatt[idx], s = sr[idx], c = kv[idx];
    out[idx] = make_float4(fmaf(s.x, c.x, a.x), fmaf(s.y, c.y, a.y),
                           fmaf(s.z, c.z, a.z), fmaf(s.w, c.w, a.w));
}

// ------------------------------------------------------------------
// Launch
// ------------------------------------------------------------------
extern "C" void kernel_launch(void* const* d_in, const int* in_sizes, int n_in,
                              void* d_out, int out_size)
{
    const float* x        = (const float*)d_in[0];
    const float* ln0_w    = (const float*)d_in[1];
    const float* ln0_b    = (const float*)d_in[2];
    const float* ln1_w    = (const float*)d_in[3];
    const float* ln1_b    = (const float*)d_in[4];
    const float* ln2_w    = (const float*)d_in[5];
    const float* ln2_b    = (const float*)d_in[6];
    const float* att_tmk  = (const float*)d_in[7];
    const float* att_tmv  = (const float*)d_in[8];
    const float* att_tmr  = (const float*)d_in[9];
    const float* att_tmg  = (const float*)d_in[10];
    const float* att_decay= (const float*)d_in[11];
    const float* att_faaaa= (const float*)d_in[12];
    const float* att_Wr   = (const float*)d_in[13];
    const float* att_Wk   = (const float*)d_in[14];
    const float* att_Wv   = (const float*)d_in[15];
    const float* att_Wg   = (const float*)d_in[16];
    const float* att_Wo   = (const float*)d_in[17];
    const float* lnx_w    = (const float*)d_in[18];
    const float* lnx_b    = (const float*)d_in[19];
    const float* ffn_tmk  = (const float*)d_in[20];
    const float* ffn_tmr  = (const float*)d_in[21];
    const float* ffn_Wk   = (const float*)d_in[22];
    const float* ffn_Wr   = (const float*)d_in[23];
    const float* ffn_Wv   = (const float*)d_in[24];

    float* base = nullptr;
    cudaGetSymbolAddress((void**)&base, g_bufs);
    float* FB = nullptr;
    cudaGetSymbolAddress((void**)&FB, g_ffnb);
    float* B0 = base + 0 * (size_t)BT * CC;
    float* B1 = base + 1 * (size_t)BT * CC;
    float* B2 = base + 2 * (size_t)BT * CC;
    float* B3 = base + 3 * (size_t)BT * CC;
    float* B4 = base + 4 * (size_t)BT * CC;
    float* B5 = base + 5 * (size_t)BT * CC;
    float* B6 = base + 6 * (size_t)BT * CC;
    float* B7 = base + 7 * (size_t)BT * CC;
    float* out = (float*)d_out;

    cudaFuncSetAttribute(gemm_mma<0>, cudaFuncAttributeMaxDynamicSharedMemorySize, GM_SMEM);
    cudaFuncSetAttribute(gemm_mma<1>, cudaFuncAttributeMaxDynamicSharedMemorySize, GM_SMEM);
    cudaFuncSetAttribute(gemm_mma<2>, cudaFuncAttributeMaxDynamicSharedMemorySize, GM_SMEM);
    cudaFuncSetAttribute(gemm_mma<3>, cudaFuncAttributeMaxDynamicSharedMemorySize, GM_SMEM);

    int eg4 = (BT * CC / 4) / 256;            // float4 elementwise grid
    dim3 gC(CC / 128, BT / 128);              // N=1024 GEMMs
    dim3 gF(FFND / 128, BT / 128);            // N=3584 GEMM

    // ln0 -> B0 (residual), ln1 -> B1
    ln0ln1_kernel<<<BT, 256>>>(x, ln0_w, ln0_b, ln1_w, ln1_b, B0, B1);
    // token-shift mixes: xk=B2, xv=B3, xr=B4, xg=B5
    mix4_kernel<<<eg4, 256>>>((const float4*)B1,
        (const float4*)att_tmk, (const float4*)att_tmv,
        (const float4*)att_tmr, (const float4*)att_tmg,
        (float4*)B2, (float4*)B3, (float4*)B4, (float4*)B5);
    // projections
    gemm_mma<0><<<gC, 256, GM_SMEM>>>(B4, att_Wr, nullptr, B6, BT, CC, CC);   // r
    gemm_mma<0><<<gC, 256, GM_SMEM>>>(B2, att_Wk, nullptr, B7, BT, CC, CC);   // k
    gemm_mma<0><<<gC, 256, GM_SMEM>>>(B3, att_Wv, nullptr, B1, BT, CC, CC);   // v
    gemm_mma<1><<<gC, 256, GM_SMEM>>>(B5, att_Wg, nullptr, B2, BT, CC, CC);   // g = silu
    // wkv recurrence -> B3
    wkv5_kernel<<<BQ * HH, 256>>>(B6, B7, B1, att_decay, att_faaaa, B3);
    // groupnorm(y/8) * g -> B4
    gn_gate_kernel<<<BT, 256>>>(B3, B2, lnx_w, lnx_b, B4);
    // x_att = x0 + (gy) @ Wo^T -> B5
    gemm_mma<0><<<gC, 256, GM_SMEM>>>(B4, att_Wo, B0, B5, BT, CC, CC);
    // channel mix
    ln_kernel<<<BT, 256>>>(B5, ln2_w, ln2_b, B1);
    mix2_kernel<<<eg4, 256>>>((const float4*)B1,
        (const float4*)ffn_tmk, (const float4*)ffn_tmr,
        (float4*)B2, (float4*)B3);                              // xk=B2, xr=B3
    gemm_mma<2><<<gF, 256, GM_SMEM>>>(B2, ffn_Wk, nullptr, FB, BT, FFND, CC); // relu^2
    gemm_mma<0><<<gC, 256, GM_SMEM>>>(FB, ffn_Wv, nullptr, B6, BT, CC, FFND); // kv
    gemm_mma<3><<<gC, 256, GM_SMEM>>>(B3, ffn_Wr, nullptr, B7, BT, CC, CC);   // sigmoid(r)
    final_kernel<<<eg4, 256>>>((const float4*)B5, (const float4*)B7,
                               (const float4*)B6, (float4*)out);
}

// round 6
// speedup vs baseline: 4.6076x; 1.4220x over previous
#include <cuda_runtime.h>
#include <cuda_fp16.h>
#include <math.h>
#include <stdint.h>

#define BQ  8
#define TT  2048
#define CC  1024
#define HH  16
#define NN  64
#define FFND 3584
#define BT  (BQ*TT)
#define EPSV 1e-5f
#define CCSQ ((size_t)CC * CC)

// ------------------------------------------------------------------
// Scratch (device globals; no dynamic allocation allowed)
// ------------------------------------------------------------------
__device__ __align__(256) float  g_bufs[8][(size_t)BT * CC];        // fp32 scratch
__device__ __align__(256) __half g_h[4][(size_t)BT * CC];           // fp16 activations
__device__ __align__(256) __half g_fh[(size_t)BT * FFND];           // fp16 FFN buffer
__device__ __align__(256) __half g_wh[6 * CCSQ + 2 * (size_t)FFND * CC]; // fp16 weights

// ==================================================================
// PTX helpers
// ==================================================================
__device__ __forceinline__ uint32_t smem_u32(const void* p) {
    uint32_t a;
    asm("{ .reg .u64 t; cvta.to.shared.u64 t, %1; cvt.u32.u64 %0, t; }" : "=r"(a) : "l"(p));
    return a;
}
__device__ __forceinline__ void cp16(uint32_t dst, const void* src) {
    asm volatile("cp.async.cg.shared.global [%0], [%1], 16;" :: "r"(dst), "l"(src));
}
#define CP_COMMIT() asm volatile("cp.async.commit_group;" ::: "memory")
#define CP_WAIT(n)  asm volatile("cp.async.wait_group %0;" :: "n"(n) : "memory")

__device__ __forceinline__ void ldsm4(uint32_t& r0, uint32_t& r1, uint32_t& r2,
                                      uint32_t& r3, uint32_t addr) {
    asm volatile("ldmatrix.sync.aligned.m8n8.x4.shared.b16 {%0,%1,%2,%3}, [%4];"
                 : "=r"(r0), "=r"(r1), "=r"(r2), "=r"(r3) : "r"(addr));
}
__device__ __forceinline__ void mma_f16(float* c, const uint32_t* a, const uint32_t* b) {
    asm volatile("mma.sync.aligned.m16n8k16.row.col.f32.f16.f16.f32 "
                 "{%0,%1,%2,%3}, {%4,%5,%6,%7}, {%8,%9}, {%0,%1,%2,%3};"
                 : "+f"(c[0]), "+f"(c[1]), "+f"(c[2]), "+f"(c[3])
                 : "r"(a[0]), "r"(a[1]), "r"(a[2]), "r"(a[3]), "r"(b[0]), "r"(b[1]));
}
__device__ __forceinline__ uint32_t swz(uint32_t off) {
    return off ^ ((off >> 3) & 0x70);   // SW128 swizzle on byte offsets
}
__device__ __forceinline__ uint32_t pack2(float a, float b) {
    __half2 h = __floats2half2_rn(a, b);
    return *reinterpret_cast<uint32_t*>(&h);
}

// ==================================================================
// fp16 mma.sync GEMM:  C[m,n] = sum_k A[m,k]*B[n,k]  (+res, epilogue)
// A,B fp16 K-contiguous. 128x128 CTA tile; 8 warps = 4(m) x 2(n);
// warp tile 32x64. K staged 64 halves (128B/row), SW128 swizzle,
// 3-stage cp.async ring. EPI: 0=none 1=silu 2=relu^2 3=sigmoid.
// HOUT: write C as fp16.
// ==================================================================
#define GM_SLOTSZ 32768                 // A 16KB + B 16KB per stage
#define GM_SMEM   (3 * GM_SLOTSZ)       // 98304 bytes

__device__ __forceinline__ void load_stage_h(uint32_t sa, const __half* Ab, const __half* Bb,
                                             int K, int kt, int tid) {
    #pragma unroll
    for (int i = 0; i < 4; i++) {
        int c = tid + i * 256;
        int row = c >> 3, seg = c & 7;
        uint32_t sw = swz((uint32_t)(row * 128 + seg * 16));
        cp16(sa + sw, Ab + (size_t)row * K + kt + seg * 8);
        cp16(sa + 16384 + sw, Bb + (size_t)row * K + kt + seg * 8);
    }
}

template<int EPI, bool HOUT>
__global__ void __launch_bounds__(256, 1) gemm_h(
    const __half* __restrict__ A, const __half* __restrict__ B,
    const float* __restrict__ res, void* __restrict__ Cout,
    int M, int N, int K)
{
    extern __shared__ char smem[];
    uint32_t sb = smem_u32(smem);
    int tid = threadIdx.x;
    int lane = tid & 31, warp = tid >> 5;
    int wm = warp >> 1, wn = warp & 1;      // 4 x 2 warp grid
    int bm = blockIdx.y * 128;
    int bn = blockIdx.x * 128;

    const __half* Ab = A + (size_t)bm * K;
    const __half* Bb = B + (size_t)bn * K;
    int S = K / 64;

    // ldmatrix lane addressing (canonical x4 m16k16 pattern)
    int l16 = lane & 15;
    int chb = (lane >> 4) * 16;          // 0 or 16 bytes (k0 / k8)

    float acc[2][8][4];
    #pragma unroll
    for (int i = 0; i < 2; i++)
        #pragma unroll
        for (int j = 0; j < 8; j++)
            #pragma unroll
            for (int l = 0; l < 4; l++) acc[i][j][l] = 0.f;

    load_stage_h(sb + 0 * GM_SLOTSZ, Ab, Bb, K, 0, tid);
    CP_COMMIT();
    load_stage_h(sb + 1 * GM_SLOTSZ, Ab, Bb, K, 64, tid);
    CP_COMMIT();

    for (int s = 0; s < S; s++) {
        CP_WAIT(1);
        __syncthreads();
        if (s + 2 < S)
            load_stage_h(sb + (uint32_t)((s + 2) % 3) * GM_SLOTSZ, Ab, Bb, K, (s + 2) * 64, tid);
        CP_COMMIT();

        uint32_t saA = sb + (uint32_t)(s % 3) * GM_SLOTSZ;
        uint32_t saB = saA + 16384;

        #pragma unroll
        for (int ks = 0; ks < 4; ks++) {
            uint32_t a[2][4], b[8][2];
            #pragma unroll
            for (int mf = 0; mf < 2; mf++) {
                uint32_t off = (uint32_t)((wm * 32 + mf * 16 + l16) * 128 + ks * 32 + chb);
                ldsm4(a[mf][0], a[mf][1], a[mf][2], a[mf][3], saA + swz(off));
            }
            #pragma unroll
            for (int p = 0; p < 4; p++) {
                uint32_t off = (uint32_t)((wn * 64 + p * 16 + l16) * 128 + ks * 32 + chb);
                uint32_t r0, r1, r2, r3;
                ldsm4(r0, r1, r2, r3, saB + swz(off));
                b[2 * p][0] = r0; b[2 * p][1] = r2;        // n0-7 of group
                b[2 * p + 1][0] = r1; b[2 * p + 1][1] = r3; // n8-15 of group
            }
            #pragma unroll
            for (int mf = 0; mf < 2; mf++)
                #pragma unroll
                for (int nf = 0; nf < 8; nf++)
                    mma_f16(acc[mf][nf], a[mf], b[nf]);
        }
        // next iteration's top barrier protects slot reuse
    }

    // epilogue: c0,c1 -> (row, 2c,2c+1); c2,c3 -> (row+8)
    int r0r = bm + wm * 32 + (lane >> 2);
    int cbase = bn + wn * 64 + (lane & 3) * 2;
    #pragma unroll
    for (int mf = 0; mf < 2; mf++) {
        #pragma unroll
        for (int half = 0; half < 2; half++) {
            int m = r0r + mf * 16 + half * 8;
            size_t rowoff = (size_t)m * N + cbase;
            #pragma unroll
            for (int nf = 0; nf < 8; nf++) {
                float vx = acc[mf][nf][half * 2 + 0];
                float vy = acc[mf][nf][half * 2 + 1];
                size_t o = rowoff + nf * 8;
                if (res) {
                    float2 rv = *(const float2*)(res + o);
                    vx += rv.x; vy += rv.y;
                }
                if (EPI == 1) {
                    vx = vx / (1.f + expf(-vx)); vy = vy / (1.f + expf(-vy));
                } else if (EPI == 2) {
                    vx = fmaxf(vx, 0.f); vx *= vx;
                    vy = fmaxf(vy, 0.f); vy *= vy;
                } else if (EPI == 3) {
                    vx = 1.f / (1.f + expf(-vx)); vy = 1.f / (1.f + expf(-vy));
                }
                if (HOUT) {
                    *(uint32_t*)((__half*)Cout + o) = pack2(vx, vy);
                } else {
                    *(float2*)((float*)Cout + o) = make_float2(vx, vy);
                }
            }
        }
    }
}

// ------------------------------------------------------------------
// fp32 -> fp16 conversion (for weights)
// ------------------------------------------------------------------
__global__ void __launch_bounds__(256) cvt_kernel(
    const float4* __restrict__ src, uint2* __restrict__ dst, int n4)
{
    int i = blockIdx.x * 256 + threadIdx.x;
    if (i < n4) {
        float4 v = src[i];
        dst[i] = make_uint2(pack2(v.x, v.y), pack2(v.z, v.w));
    }
}

// ------------------------------------------------------------------
// Block-wide reduction of (sum, sumsq) across 256 threads
// ------------------------------------------------------------------
__device__ __forceinline__ void block_reduce_2(float& s, float& s2) {
    __shared__ float sh[16];
    #pragma unroll
    for (int o = 16; o > 0; o >>= 1) {
        s  += __shfl_xor_sync(0xffffffffu, s,  o);
        s2 += __shfl_xor_sync(0xffffffffu, s2, o);
    }
    int wid = threadIdx.x >> 5;
    if ((threadIdx.x & 31) == 0) { sh[wid] = s; sh[8 + wid] = s2; }
    __syncthreads();
    float a = 0.f, b = 0.f;
    #pragma unroll
    for (int i = 0; i < 8; i++) { a += sh[i]; b += sh[8 + i]; }
    s = a; s2 = b;
    __syncthreads();
}

// ------------------------------------------------------------------
// Fused ln0 + ln1  (one block per row of 1024)
// ------------------------------------------------------------------
__global__ void __launch_bounds__(256) ln0ln1_kernel(
    const float* __restrict__ x,
    const float* __restrict__ w0, const float* __restrict__ b0,
    const float* __restrict__ w1, const float* __restrict__ b1,
    float* __restrict__ x0, float* __restrict__ xn)
{
    int row = blockIdx.x;
    size_t base = (size_t)row * CC;
    float v[4];
    float s = 0.f, s2 = 0.f;
    #pragma unroll
    for (int l = 0; l < 4; l++) {
        int c = l * 256 + threadIdx.x;
        v[l] = x[base + c];
        s += v[l]; s2 += v[l] * v[l];
    }
    block_reduce_2(s, s2);
    float mu = s * (1.f / CC);
    float rstd = rsqrtf(s2 * (1.f / CC) - mu * mu + EPSV);
    s = 0.f; s2 = 0.f;
    #pragma unroll
    for (int l = 0; l < 4; l++) {
        int c = l * 256 + threadIdx.x;
        float t = (v[l] - mu) * rstd * w0[c] + b0[c];
        v[l] = t;
        x0[base + c] = t;
        s += t; s2 += t * t;
    }
    block_reduce_2(s, s2);
    mu = s * (1.f / CC);
    rstd = rsqrtf(s2 * (1.f / CC) - mu * mu + EPSV);
    #pragma unroll
    for (int l = 0; l < 4; l++) {
        int c = l * 256 + threadIdx.x;
        xn[base + c] = (v[l] - mu) * rstd * w1[c] + b1[c];
    }
}

// ------------------------------------------------------------------
// Plain layernorm (one block per row)
// ------------------------------------------------------------------
__global__ void __launch_bounds__(256) ln_kernel(
    const float* __restrict__ in,
    const float* __restrict__ w, const float* __restrict__ b,
    float* __restrict__ out)
{
    int row = blockIdx.x;
    size_t base = (size_t)row * CC;
    float v[4];
    float s = 0.f, s2 = 0.f;
    #pragma unroll
    for (int l = 0; l < 4; l++) {
        int c = l * 256 + threadIdx.x;
        v[l] = in[base + c];
        s += v[l]; s2 += v[l] * v[l];
    }
    block_reduce_2(s, s2);
    float mu = s * (1.f / CC);
    float rstd = rsqrtf(s2 * (1.f / CC) - mu * mu + EPSV);
    #pragma unroll
    for (int l = 0; l < 4; l++) {
        int c = l * 256 + threadIdx.x;
        out[base + c] = (v[l] - mu) * rstd * w[c] + b[c];
    }
}

// ------------------------------------------------------------------
// Token-shift mixes (read fp32, write fp16)
// ------------------------------------------------------------------
__global__ void __launch_bounds__(256) mix4_kernel(
    const float4* __restrict__ xn,
    const float4* __restrict__ tmk, const float4* __restrict__ tmv,
    const float4* __restrict__ tmr, const float4* __restrict__ tmg,
    uint2* __restrict__ xk, uint2* __restrict__ xv,
    uint2* __restrict__ xr, uint2* __restrict__ xg)
{
    int idx = blockIdx.x * 256 + threadIdx.x;      // in float4 units
    int c = idx & (CC / 4 - 1);
    int t = (idx >> 8) & (TT - 1);
    float4 a = xn[idx];
    float4 p = make_float4(0.f, 0.f, 0.f, 0.f);
    if (t != 0) p = xn[idx - CC / 4];
    float dx = a.x - p.x, dy = a.y - p.y, dz = a.z - p.z, dw = a.w - p.w;
    float4 m;
    m = *(const float4*)&tmk[c];
    xk[idx] = make_uint2(pack2(fmaf(dx, m.x, p.x), fmaf(dy, m.y, p.y)),
                         pack2(fmaf(dz, m.z, p.z), fmaf(dw, m.w, p.w)));
    m = *(const float4*)&tmv[c];
    xv[idx] = make_uint2(pack2(fmaf(dx, m.x, p.x), fmaf(dy, m.y, p.y)),
                         pack2(fmaf(dz, m.z, p.z), fmaf(dw, m.w, p.w)));
    m = *(const float4*)&tmr[c];
    xr[idx] = make_uint2(pack2(fmaf(dx, m.x, p.x), fmaf(dy, m.y, p.y)),
                         pack2(fmaf(dz, m.z, p.z), fmaf(dw, m.w, p.w)));
    m = *(const float4*)&tmg[c];
    xg[idx] = make_uint2(pack2(fmaf(dx, m.x, p.x), fmaf(dy, m.y, p.y)),
                         pack2(fmaf(dz, m.z, p.z), fmaf(dw, m.w, p.w)));
}

__global__ void __launch_bounds__(256) mix2_kernel(
    const float4* __restrict__ xn,
    const float4* __restrict__ tmk, const float4* __restrict__ tmr,
    uint2* __restrict__ xk, uint2* __restrict__ xr)
{
    int idx = blockIdx.x * 256 + threadIdx.x;
    int c = idx & (CC / 4 - 1);
    int t = (idx >> 8) & (TT - 1);
    float4 a = xn[idx];
    float4 p = make_float4(0.f, 0.f, 0.f, 0.f);
    if (t != 0) p = xn[idx - CC / 4];
    float dx = a.x - p.x, dy = a.y - p.y, dz = a.z - p.z, dw = a.w - p.w;
    float4 m;
    m = *(const float4*)&tmk[c];
    xk[idx] = make_uint2(pack2(fmaf(dx, m.x, p.x), fmaf(dy, m.y, p.y)),
                         pack2(fmaf(dz, m.z, p.z), fmaf(dw, m.w, p.w)));
    m = *(const float4*)&tmr[c];
    xr[idx] = make_uint2(pack2(fmaf(dx, m.x, p.x), fmaf(dy, m.y, p.y)),
                         pack2(fmaf(dz, m.z, p.z), fmaf(dw, m.w, p.w)));
}

// ------------------------------------------------------------------
// wkv5 recurrence: one block per (b,h); 256 threads.
// 3-slot cp.async ring over timesteps; one barrier per step.
// ------------------------------------------------------------------
__global__ void __launch_bounds__(256) wkv5_kernel(
    const float* __restrict__ r, const float* __restrict__ k,
    const float* __restrict__ v,
    const float* __restrict__ decay, const float* __restrict__ faaaa,
    float* __restrict__ out)
{
    int bh = blockIdx.x;
    int b = bh / HH, h = bh % HH;
    int tid = threadIdx.x;
    int j = tid >> 2, ig = tid & 3;

    float S[16], uu[16], ww[16];
    #pragma unroll
    for (int m = 0; m < 16; m++) {
        int i = ig * 16 + m;
        S[m] = 0.f;
        uu[m] = faaaa[h * NN + i];
        ww[m] = expf(-expf(decay[h * NN + i]));
    }

    __shared__ __align__(16) float buf[3 * 192];
    uint32_t sbuf = smem_u32(buf);

    size_t base = ((size_t)b * TT) * CC + h * NN;

    const float* srcs[3] = { r, k, v };
    int part = tid >> 4;
    int off4 = (tid & 15) * 4;

    #pragma unroll
    for (int t = 0; t < 2; t++) {
        if (tid < 48)
            cp16(sbuf + (uint32_t)(t * 192 + part * 64 + off4) * 4,
                 srcs[part] + base + (size_t)t * CC + off4);
        CP_COMMIT();
    }

    for (int t = 0; t < TT; t++) {
        CP_WAIT(1);
        __syncthreads();
        if (t + 2 < TT && tid < 48)
            cp16(sbuf + (uint32_t)(((t + 2) % 3) * 192 + part * 64 + off4) * 4,
                 srcs[part] + base + (size_t)(t + 2) * CC + off4);
        CP_COMMIT();

        const float* sl = buf + (t % 3) * 192;
        float vj = sl[128 + j];
        float y = 0.f;
        #pragma unroll
        for (int m = 0; m < 16; m++) {
            int i = ig * 16 + m;
            float a = sl[64 + i] * vj;
            y = fmaf(sl[i], fmaf(uu[m], a, S[m]), y);
            S[m] = fmaf(ww[m], S[m], a);
        }
        y += __shfl_xor_sync(0xffffffffu, y, 1);
        y += __shfl_xor_sync(0xffffffffu, y, 2);
        if (ig == 0) out[base + (size_t)t * CC + j] = y;
    }
}

// ------------------------------------------------------------------
// GroupNorm(y/8) * g  -> fp16 output (one block per row)
// ------------------------------------------------------------------
__global__ void __launch_bounds__(256) gn_gate_kernel(
    const float* __restrict__ y, const float* __restrict__ g,
    const float* __restrict__ w, const float* __restrict__ b,
    __half* __restrict__ out)
{
    int row = blockIdx.x;
    size_t base = (size_t)row * CC;
    int gi = threadIdx.x >> 4;
    int sub = threadIdx.x & 15;
    float v[4];
    float s = 0.f, s2 = 0.f;
    #pragma unroll
    for (int l = 0; l < 4; l++) {
        int c = gi * 64 + l * 16 + sub;
        v[l] = y[base + c] * 0.125f;
        s += v[l]; s2 += v[l] * v[l];
    }
    #pragma unroll
    for (int o = 8; o > 0; o >>= 1) {
        s  += __shfl_xor_sync(0xffffffffu, s,  o);
        s2 += __shfl_xor_sync(0xffffffffu, s2, o);
    }
    float mu = s * (1.f / 64);
    float rstd = rsqrtf(s2 * (1.f / 64) - mu * mu + EPSV);
    #pragma unroll
    for (int l = 0; l < 4; l++) {
        int c = gi * 64 + l * 16 + sub;
        float val = ((v[l] - mu) * rstd * w[c] + b[c]) * g[base + c];
        out[base + c] = __float2half(val);
    }
}

// ------------------------------------------------------------------
// out = xatt + sigmoid_r * kv   (float4)
// ------------------------------------------------------------------
__global__ void __launch_bounds__(256) final_kernel(
    const float4* __restrict__ xatt, const float4* __restrict__ sr,
    const float4* __restrict__ kv, float4* __restrict__ out)
{
    int idx = blockIdx.x * 256 + threadIdx.x;
    float4 a = xatt[idx], s = sr[idx], c = kv[idx];
    out[idx] = make_float4(fmaf(s.x, c.x, a.x), fmaf(s.y, c.y, a.y),
                           fmaf(s.z, c.z, a.z), fmaf(s.w, c.w, a.w));
}

// ------------------------------------------------------------------
// Launch
// ------------------------------------------------------------------
extern "C" void kernel_launch(void* const* d_in, const int* in_sizes, int n_in,
                              void* d_out, int out_size)
{
    const float* x        = (const float*)d_in[0];
    const float* ln0_w    = (const float*)d_in[1];
    const float* ln0_b    = (const float*)d_in[2];
    const float* ln1_w    = (const float*)d_in[3];
    const float* ln1_b    = (const float*)d_in[4];
    const float* ln2_w    = (const float*)d_in[5];
    const float* ln2_b    = (const float*)d_in[6];
    const float* att_tmk  = (const float*)d_in[7];
    const float* att_tmv  = (const float*)d_in[8];
    const float* att_tmr  = (const float*)d_in[9];
    const float* att_tmg  = (const float*)d_in[10];
    const float* att_decay= (const float*)d_in[11];
    const float* att_faaaa= (const float*)d_in[12];
    const float* att_Wr   = (const float*)d_in[13];
    const float* att_Wk   = (const float*)d_in[14];
    const float* att_Wv   = (const float*)d_in[15];
    const float* att_Wg   = (const float*)d_in[16];
    const float* att_Wo   = (const float*)d_in[17];
    const float* lnx_w    = (const float*)d_in[18];
    const float* lnx_b    = (const float*)d_in[19];
    const float* ffn_tmk  = (const float*)d_in[20];
    const float* ffn_tmr  = (const float*)d_in[21];
    const float* ffn_Wk   = (const float*)d_in[22];
    const float* ffn_Wr   = (const float*)d_in[23];
    const float* ffn_Wv   = (const float*)d_in[24];

    float* base = nullptr;
    cudaGetSymbolAddress((void**)&base, g_bufs);
    __half* H = nullptr;
    cudaGetSymbolAddress((void**)&H, g_h);
    __half* FH = nullptr;
    cudaGetSymbolAddress((void**)&FH, g_fh);
    __half* WH = nullptr;
    cudaGetSymbolAddress((void**)&WH, g_wh);

    float* B0 = base + 0 * (size_t)BT * CC;
    float* B1 = base + 1 * (size_t)BT * CC;
    float* B2 = base + 2 * (size_t)BT * CC;
    float* B3 = base + 3 * (size_t)BT * CC;
    float* B5 = base + 5 * (size_t)BT * CC;
    float* B6 = base + 6 * (size_t)BT * CC;
    float* B7 = base + 7 * (size_t)BT * CC;
    __half* H0 = H + 0 * (size_t)BT * CC;
    __half* H1 = H + 1 * (size_t)BT * CC;
    __half* H2 = H + 2 * (size_t)BT * CC;
    __half* H3 = H + 3 * (size_t)BT * CC;
    __half* WHr = WH + 0 * CCSQ;
    __half* WHk = WH + 1 * CCSQ;
    __half* WHv = WH + 2 * CCSQ;
    __half* WHg = WH + 3 * CCSQ;
    __half* WHo = WH + 4 * CCSQ;
    __half* WHfr = WH + 5 * CCSQ;
    __half* WHfk = WH + 6 * CCSQ;
    __half* WHfv = WHfk + (size_t)FFND * CC;
    float* out = (float*)d_out;

    cudaFuncSetAttribute(gemm_h<0,false>, cudaFuncAttributeMaxDynamicSharedMemorySize, GM_SMEM);
    cudaFuncSetAttribute(gemm_h<1,false>, cudaFuncAttributeMaxDynamicSharedMemorySize, GM_SMEM);
    cudaFuncSetAttribute(gemm_h<2,true>,  cudaFuncAttributeMaxDynamicSharedMemorySize, GM_SMEM);
    cudaFuncSetAttribute(gemm_h<3,false>, cudaFuncAttributeMaxDynamicSharedMemorySize, GM_SMEM);

    int eg4 = (BT * CC / 4) / 256;            // float4 elementwise grid
    dim3 gC(CC / 128, BT / 128);              // N=1024 GEMMs
    dim3 gF(FFND / 128, BT / 128);            // N=3584 GEMM
    int cg = (CCSQ / 4 + 255) / 256;          // CCxCC convert grid
    int fg = ((size_t)FFND * CC / 4 + 255) / 256;

    // weight conversions (independent of the activation chain)
    cvt_kernel<<<cg, 256>>>((const float4*)att_Wr, (uint2*)WHr, CCSQ / 4);
    cvt_kernel<<<cg, 256>>>((const float4*)att_Wk, (uint2*)WHk, CCSQ / 4);
    cvt_kernel<<<cg, 256>>>((const float4*)att_Wv, (uint2*)WHv, CCSQ / 4);
    cvt_kernel<<<cg, 256>>>((const float4*)att_Wg, (uint2*)WHg, CCSQ / 4);
    cvt_kernel<<<cg, 256>>>((const float4*)att_Wo, (uint2*)WHo, CCSQ / 4);
    cvt_kernel<<<cg, 256>>>((const float4*)ffn_Wr, (uint2*)WHfr, CCSQ / 4);
    cvt_kernel<<<fg, 256>>>((const float4*)ffn_Wk, (uint2*)WHfk, FFND * CC / 4);
    cvt_kernel<<<fg, 256>>>((const float4*)ffn_Wv, (uint2*)WHfv, FFND * CC / 4);

    // ln0 -> B0 (residual), ln1 -> B1
    ln0ln1_kernel<<<BT, 256>>>(x, ln0_w, ln0_b, ln1_w, ln1_b, B0, B1);
    // token-shift mixes (fp16 out): xk=H0, xv=H1, xr=H2, xg=H3
    mix4_kernel<<<eg4, 256>>>((const float4*)B1,
        (const float4*)att_tmk, (const float4*)att_tmv,
        (const float4*)att_tmr, (const float4*)att_tmg,
        (uint2*)H0, (uint2*)H1, (uint2*)H2, (uint2*)H3);
    // projections (fp32 out)
    gemm_h<0,false><<<gC, 256, GM_SMEM>>>(H2, WHr, nullptr, B6, BT, CC, CC);   // r
    gemm_h<0,false><<<gC, 256, GM_SMEM>>>(H0, WHk, nullptr, B7, BT, CC, CC);   // k
    gemm_h<0,false><<<gC, 256, GM_SMEM>>>(H1, WHv, nullptr, B1, BT, CC, CC);   // v
    gemm_h<1,false><<<gC, 256, GM_SMEM>>>(H3, WHg, nullptr, B2, BT, CC, CC);   // g = silu
    // wkv recurrence -> B3
    wkv5_kernel<<<BQ * HH, 256>>>(B6, B7, B1, att_decay, att_faaaa, B3);
    // groupnorm(y/8) * g -> H0 (fp16)
    gn_gate_kernel<<<BT, 256>>>(B3, B2, lnx_w, lnx_b, H0);
    // x_att = x0 + (gy) @ Wo^T -> B5
    gemm_h<0,false><<<gC, 256, GM_SMEM>>>(H0, WHo, B0, B5, BT, CC, CC);
    // channel mix
    ln_kernel<<<BT, 256>>>(B5, ln2_w, ln2_b, B1);
    mix2_kernel<<<eg4, 256>>>((const float4*)B1,
        (const float4*)ffn_tmk, (const float4*)ffn_tmr,
        (uint2*)H1, (uint2*)H2);                                // xk=H1, xr=H2
    gemm_h<2,true><<<gF, 256, GM_SMEM>>>(H1, WHfk, nullptr, FH, BT, FFND, CC); // relu^2 (fp16 out)
    gemm_h<0,false><<<gC, 256, GM_SMEM>>>(FH, WHfv, nullptr, B6, BT, CC, FFND); // kv
    gemm_h<3,false><<<gC, 256, GM_SMEM>>>(H2, WHfr, nullptr, B7, BT, CC, CC);  // sigmoid(r)
    final_kernel<<<eg4, 256>>>((const float4*)B5, (const float4*)B7,
                               (const float4*)B6, (float4*)out);
}